// round 13
// baseline (speedup 1.0000x reference)
#include <cuda_runtime.h>
#include <cuda_fp16.h>
#include <cstdint>

// ---------------- problem constants ----------------
#define N_TOK 8192
#define DIM   1024
#define NEXP  8

// ---------------- GEMM tiling ----------------
#define BM 128               // rows per CTA
#define BN 128               // cols per CTA
#define BK 64                // k (halves) per stage
#define NK (DIM / BK)        // 16 k-stages
#define NSTAGE 3

#define A_ROWB 144           // bytes per A smem row (128 data + 16 pad)
#define B_ROWB 272           // bytes per B smem row (256 data + 16 pad)
#define ASZ (BM * A_ROWB)    // 18432 B per stage
#define BSZ (BK * B_ROWB)    // 17408 B per stage

#define SM_TOK 0
#define SM_A   512
#define SM_B   (SM_A + NSTAGE * ASZ)          // 55808
#define SMEM_ALLOC (SM_B + NSTAGE * BSZ)      // 108032 B (2 CTAs/SM)

// ---------------- scratch ----------------
__device__ int    g_cnt[NEXP];
__device__ int    g_off[NEXP];
__device__ int    g_tok[NEXP * N_TOK];
__device__ int    g_texp[N_TOK * 2];
__device__ int    g_slot[N_TOK * 2];
__device__ float  g_twt [N_TOK * 2];
__device__ __half g_xh[N_TOK * DIM];         // x in fp16
__device__ __half g_wh[NEXP * DIM * DIM];    // W in fp16 (k-major)
__device__ float  g_y [2 * N_TOK * DIM];     // per (expert,slot) GEMM result

// ---------------- helpers ----------------
__device__ __forceinline__ uint32_t smem_u32(const void* p) {
    uint32_t a;
    asm("{ .reg .u64 t; cvta.to.shared.u64 t, %1; cvt.u32.u64 %0, t; }"
        : "=r"(a) : "l"(p));
    return a;
}
__device__ __forceinline__ void cp16(uint32_t dst, const void* src) {
    asm volatile("cp.async.cg.shared.global [%0], [%1], 16;" :: "r"(dst), "l"(src));
}
#define CP_COMMIT() asm volatile("cp.async.commit_group;" ::: "memory")
#define CP_WAIT(n)  asm volatile("cp.async.wait_group %0;" :: "n"(n) : "memory")

__device__ __forceinline__ void ldsm4(uint32_t* r, uint32_t addr) {
    asm volatile(
        "ldmatrix.sync.aligned.m8n8.x4.shared.b16 {%0,%1,%2,%3}, [%4];"
        : "=r"(r[0]), "=r"(r[1]), "=r"(r[2]), "=r"(r[3]) : "r"(addr));
}
__device__ __forceinline__ void ldsm4t(uint32_t* r, uint32_t addr) {
    asm volatile(
        "ldmatrix.sync.aligned.m8n8.x4.trans.shared.b16 {%0,%1,%2,%3}, [%4];"
        : "=r"(r[0]), "=r"(r[1]), "=r"(r[2]), "=r"(r[3]) : "r"(addr));
}
__device__ __forceinline__ void mma_f16(float* c, const uint32_t* a,
                                        uint32_t b0, uint32_t b1) {
    asm volatile(
        "mma.sync.aligned.m16n8k16.row.col.f32.f16.f16.f32 "
        "{%0,%1,%2,%3}, {%4,%5,%6,%7}, {%8,%9}, {%0,%1,%2,%3};"
        : "+f"(c[0]), "+f"(c[1]), "+f"(c[2]), "+f"(c[3])
        : "r"(a[0]), "r"(a[1]), "r"(a[2]), "r"(a[3]), "r"(b0), "r"(b1));
}

// ---------------- kernel: zero counters ----------------
__global__ void zero_cnt_kernel() {
    if (threadIdx.x < NEXP) g_cnt[threadIdx.x] = 0;
}

// ---------------- kernel: fused prepass ----------------
// blocks [0, 1024): gating + x fp16 convert
// blocks [1024, 5120): W fp16 convert
__global__ void prepass_kernel(const float* __restrict__ x,
                               const float* __restrict__ gW,
                               const float* __restrict__ gb,
                               const float* __restrict__ eW) {
    __shared__ float sW[DIM * 9];
    int tid = threadIdx.x;

    if (blockIdx.x >= (N_TOK / 8)) {
        // ---- W convert path ----
        size_t i = ((size_t)(blockIdx.x - N_TOK / 8) * 256 + tid) * 8;
        float4 v0 = *(const float4*)(eW + i);
        float4 v1 = *(const float4*)(eW + i + 4);
        __half2 h[4];
        h[0] = __floats2half2_rn(v0.x, v0.y);
        h[1] = __floats2half2_rn(v0.z, v0.w);
        h[2] = __floats2half2_rn(v1.x, v1.y);
        h[3] = __floats2half2_rn(v1.z, v1.w);
        *(uint4*)(g_wh + i) = *(uint4*)h;
        return;
    }

    // ---- gating path ----
    for (int i = tid; i < DIM * NEXP; i += 256) {
        int d = i >> 3, e = i & 7;
        sW[d * 9 + e] = gW[i];
    }
    __syncthreads();

    int warp = tid >> 5, lane = tid & 31;
    int t = blockIdx.x * 8 + warp;
    const float* xrow = x + (size_t)t * DIM;
    __half*      xout = g_xh + (size_t)t * DIM;

    float acc[NEXP];
#pragma unroll
    for (int e = 0; e < NEXP; e++) acc[e] = 0.f;
#pragma unroll 8
    for (int i = 0; i < 32; i++) {
        int d = i * 32 + lane;
        float xv = xrow[d];
        xout[d] = __float2half_rn(xv);
        const float* w = &sW[d * 9];
#pragma unroll
        for (int e = 0; e < NEXP; e++) acc[e] += xv * w[e];
    }
#pragma unroll
    for (int e = 0; e < NEXP; e++) {
#pragma unroll
        for (int off = 16; off > 0; off >>= 1)
            acc[e] += __shfl_down_sync(0xFFFFFFFFu, acc[e], off);
    }

    if (lane == 0) {
        float s[NEXP], p[NEXP];
        float m = -1e30f;
#pragma unroll
        for (int e = 0; e < NEXP; e++) {
            s[e] = fmaxf(acc[e] + gb[e], 1e-4f);
            m = fmaxf(m, s[e]);
        }
        float sum = 0.f;
#pragma unroll
        for (int e = 0; e < NEXP; e++) { p[e] = expf(s[e] - m); sum += p[e]; }
        float inv = 1.f / sum;

        int b1 = 0, b2 = -1;
        float v1 = -1.f, v2 = -1.f;
#pragma unroll
        for (int e = 0; e < NEXP; e++) {
            float pe = p[e] * inv;
            if (pe > v1)      { v2 = v1; b2 = b1; v1 = pe; b1 = e; }
            else if (pe > v2) { v2 = pe; b2 = e; }
        }
        float c1 = fmaxf(v1, 0.1f);
        float c2 = fmaxf(v2, 0.1f);
        float a  = 1.f / ((c1 + c2) * 2.0f);
        float a1 = c1 * a, a2 = c2 * a;

        int s1 = atomicAdd(&g_cnt[b1], 1);
        g_tok[b1 * N_TOK + s1] = t;
        int s2 = atomicAdd(&g_cnt[b2], 1);
        g_tok[b2 * N_TOK + s2] = t;

        g_texp[2 * t] = b1;  g_texp[2 * t + 1] = b2;
        g_slot[2 * t] = s1;  g_slot[2 * t + 1] = s2;
        g_twt [2 * t] = a1;  g_twt [2 * t + 1] = a2;
    }
}

// ---------------- kernel: prefix offsets ----------------
__global__ void scan_kernel() {
    if (threadIdx.x == 0) {
        int o = 0;
        for (int e = 0; e < NEXP; e++) { g_off[e] = o; o += g_cnt[e]; }
    }
}

// ---------------- kernel: fp16 mma.sync gathered GEMM ----------------
__global__ __launch_bounds__(256, 2)
void moe_gemm_mma() {
    extern __shared__ char smem[];
    int e     = blockIdx.z;
    int cnt   = g_cnt[e];
    int tile0 = blockIdx.y * BM;
    if (tile0 >= cnt) return;
    int f0  = blockIdx.x * BN;
    int tid = threadIdx.x;
    int wid = tid >> 5, lane = tid & 31;
    int g = lane >> 2, t = lane & 3;
    int wm = wid & 3, wn = wid >> 2;        // warp tile: 32 rows x 64 cols

    uint32_t sb = smem_u32(smem);
    int* s_tok = (int*)(smem + SM_TOK);
    for (int i = tid; i < BM; i += 256) {
        int r = tile0 + i;
        s_tok[i] = g_tok[e * N_TOK + (r < cnt ? r : 0)];
    }
    __syncthreads();

    // ---- loader base pointers ----
    int ar = tid >> 1, ah = tid & 1;                 // A: 2 threads/row, 64B each
    const __half* aSrc = g_xh + (size_t)s_tok[ar] * DIM + ah * 32;
    uint32_t      aDst = sb + SM_A + ar * A_ROWB + ah * 64;
    int bkr = tid >> 2, bc = tid & 3;                // B: 4 threads/k-row, 64B each
    const __half* bSrc = g_wh + ((size_t)e << 20) + (size_t)bkr * DIM + f0 + bc * 32;
    uint32_t      bDst = sb + SM_B + bkr * B_ROWB + bc * 64;

#define LOAD_STAGE(slot, s)                                              \
    do {                                                                 \
        int k0_ = (s) * BK;                                              \
        const __half* sa_ = aSrc + k0_;                                  \
        uint32_t da_ = aDst + (slot) * ASZ;                              \
        cp16(da_, sa_);      cp16(da_ + 16, sa_ + 8);                    \
        cp16(da_ + 32, sa_ + 16); cp16(da_ + 48, sa_ + 24);              \
        const __half* sb_ = bSrc + (size_t)k0_ * DIM;                    \
        uint32_t db_ = bDst + (slot) * BSZ;                              \
        cp16(db_, sb_);      cp16(db_ + 16, sb_ + 8);                    \
        cp16(db_ + 32, sb_ + 16); cp16(db_ + 48, sb_ + 24);              \
        CP_COMMIT();                                                     \
    } while (0)

    // ---- ldmatrix per-thread addresses ----
    int lrow  = lane & 15;          // row within 16-row group
    int lchnk = (lane >> 4) * 16;   // +16B for matrices 2,3
    uint32_t aLdBase = sb + SM_A + (uint32_t)((wm * 32 + lrow) * A_ROWB + lchnk);
    uint32_t bLdBase = sb + SM_B + (uint32_t)(lrow * B_ROWB + wn * 128 + lchnk);

    float acc[2][8][4];
#pragma unroll
    for (int i = 0; i < 2; i++)
#pragma unroll
        for (int j = 0; j < 8; j++)
#pragma unroll
            for (int q = 0; q < 4; q++) acc[i][j][q] = 0.f;

#pragma unroll
    for (int p = 0; p < NSTAGE - 1; p++) LOAD_STAGE(p, p);

    for (int s = 0; s < NK; s++) {
        CP_WAIT(NSTAGE - 2);
        __syncthreads();
        if (s + NSTAGE - 1 < NK) {
            LOAD_STAGE((s + NSTAGE - 1) % NSTAGE, s + NSTAGE - 1);
        } else {
            CP_COMMIT();
        }

        int slot = s % NSTAGE;
        uint32_t aL = aLdBase + slot * ASZ;
        uint32_t bL = bLdBase + slot * BSZ;
#pragma unroll
        for (int ks = 0; ks < 4; ks++) {
            uint32_t a[2][4], bq[4][4];
#pragma unroll
            for (int i = 0; i < 2; i++)
                ldsm4(a[i], aL + i * (16 * A_ROWB) + ks * 32);
#pragma unroll
            for (int jj = 0; jj < 4; jj++)
                ldsm4t(bq[jj], bL + ks * (16 * B_ROWB) + jj * 32);
#pragma unroll
            for (int jj = 0; jj < 4; jj++)
#pragma unroll
                for (int i = 0; i < 2; i++) {
                    mma_f16(acc[i][2 * jj],     a[i], bq[jj][0], bq[jj][1]);
                    mma_f16(acc[i][2 * jj + 1], a[i], bq[jj][2], bq[jj][3]);
                }
        }
    }

    // ---- epilogue: write to staging y ----
    int rowbase = g_off[e] + tile0;
#pragma unroll
    for (int i = 0; i < 2; i++) {
        int r0 = wm * 32 + i * 16 + g;
#pragma unroll
        for (int j = 0; j < 8; j++) {
            int col = f0 + wn * 64 + j * 8 + t * 2;
            if (tile0 + r0 < cnt) {
                float2 v = make_float2(acc[i][j][0], acc[i][j][1]);
                *(float2*)(g_y + (size_t)(rowbase + r0) * DIM + col) = v;
            }
            if (tile0 + r0 + 8 < cnt) {
                float2 v = make_float2(acc[i][j][2], acc[i][j][3]);
                *(float2*)(g_y + (size_t)(rowbase + r0 + 8) * DIM + col) = v;
            }
        }
    }
#undef LOAD_STAGE
}

// ---------------- kernel: combine ----------------
__global__ void combine_kernel(const float* __restrict__ eb,
                               float* __restrict__ out) {
    int tid = blockIdx.x * 256 + threadIdx.x;
    int t = tid >> 6, j = tid & 63;
    int e1 = g_texp[2 * t], e2 = g_texp[2 * t + 1];
    float a1 = g_twt[2 * t], a2 = g_twt[2 * t + 1];
    int r1 = g_off[e1] + g_slot[2 * t];
    int r2 = g_off[e2] + g_slot[2 * t + 1];
    const float4* y1 = (const float4*)(g_y + (size_t)r1 * DIM);
    const float4* y2 = (const float4*)(g_y + (size_t)r2 * DIM);
    const float4* b1 = (const float4*)(eb + (size_t)e1 * DIM);
    const float4* b2 = (const float4*)(eb + (size_t)e2 * DIM);
    float4* o = (float4*)(out + (size_t)t * DIM);
#pragma unroll
    for (int q = 0; q < 4; q++) {
        int f = j + 64 * q;
        float4 v1 = y1[f], v2 = y2[f], c1 = b1[f], c2 = b2[f];
        float4 r;
        r.x = a1 * (v1.x + c1.x) + a2 * (v2.x + c2.x);
        r.y = a1 * (v1.y + c1.y) + a2 * (v2.y + c2.y);
        r.z = a1 * (v1.z + c1.z) + a2 * (v2.z + c2.z);
        r.w = a1 * (v1.w + c1.w) + a2 * (v2.w + c2.w);
        o[f] = r;
    }
}

// ---------------- launch ----------------
extern "C" void kernel_launch(void* const* d_in, const int* in_sizes, int n_in,
                              void* d_out, int out_size) {
    const float* x  = (const float*)d_in[0];
    const float* gW = (const float*)d_in[1];
    const float* gb = (const float*)d_in[2];
    const float* eW = (const float*)d_in[3];
    const float* eb = (const float*)d_in[4];
    float* out = (float*)d_out;
    (void)in_sizes; (void)n_in; (void)out_size;

    zero_cnt_kernel<<<1, 32>>>();
    prepass_kernel<<<N_TOK / 8 + (NEXP * DIM * DIM / 8) / 256, 256>>>(x, gW, gb, eW);
    scan_kernel<<<1, 1>>>();

    cudaFuncSetAttribute(moe_gemm_mma,
                         cudaFuncAttributeMaxDynamicSharedMemorySize, SMEM_ALLOC);
    moe_gemm_mma<<<dim3(DIM / BN, N_TOK / BM, NEXP), 256, SMEM_ALLOC>>>();

    combine_kernel<<<(N_TOK * 64) / 256, 256>>>(eb, out);
}

// round 14
// speedup vs baseline: 1.2354x; 1.2354x over previous
#include <cuda_runtime.h>
#include <cuda_fp16.h>
#include <cstdint>

// ---------------- problem constants ----------------
#define N_TOK 8192
#define DIM   1024
#define NEXP  8

// ---------------- GEMM tiling ----------------
#define BM 128               // rows per CTA
#define BN 128               // cols per CTA
#define BK 32                // k (halves) per stage
#define NK (DIM / BK)        // 32 k-stages
#define NSTAGE 5

#define A_ROWB 80            // bytes per A smem row (64 data + 16 pad)
#define B_ROWB 272           // bytes per B smem row (256 data + 16 pad)
#define ASZ (BM * A_ROWB)    // 10240 B per stage
#define BSZ (BK * B_ROWB)    // 8704 B per stage

#define SM_TOK 0
#define SM_A   512
#define SM_B   (SM_A + NSTAGE * ASZ)          // 51712
#define SMEM_ALLOC (SM_B + NSTAGE * BSZ)      // 95232 B (2 CTAs/SM)

// ---------------- scratch ----------------
__device__ int    g_cnt[NEXP];
__device__ int    g_off[NEXP];
__device__ int    g_tok[NEXP * N_TOK];
__device__ int    g_texp[N_TOK * 2];
__device__ int    g_slot[N_TOK * 2];
__device__ float  g_twt [N_TOK * 2];
__device__ __half g_xh[N_TOK * DIM];         // x in fp16
__device__ __half g_wh[NEXP * DIM * DIM];    // W in fp16 (k-major)
__device__ __half g_yh[2 * N_TOK * DIM];     // per (expert,slot) GEMM result (fp16)

// ---------------- helpers ----------------
__device__ __forceinline__ uint32_t smem_u32(const void* p) {
    uint32_t a;
    asm("{ .reg .u64 t; cvta.to.shared.u64 t, %1; cvt.u32.u64 %0, t; }"
        : "=r"(a) : "l"(p));
    return a;
}
__device__ __forceinline__ void cp16(uint32_t dst, const void* src) {
    asm volatile("cp.async.cg.shared.global [%0], [%1], 16;" :: "r"(dst), "l"(src));
}
#define CP_COMMIT() asm volatile("cp.async.commit_group;" ::: "memory")
#define CP_WAIT(n)  asm volatile("cp.async.wait_group %0;" :: "n"(n) : "memory")

__device__ __forceinline__ void ldsm4(uint32_t* r, uint32_t addr) {
    asm volatile(
        "ldmatrix.sync.aligned.m8n8.x4.shared.b16 {%0,%1,%2,%3}, [%4];"
        : "=r"(r[0]), "=r"(r[1]), "=r"(r[2]), "=r"(r[3]) : "r"(addr));
}
__device__ __forceinline__ void ldsm4t(uint32_t* r, uint32_t addr) {
    asm volatile(
        "ldmatrix.sync.aligned.m8n8.x4.trans.shared.b16 {%0,%1,%2,%3}, [%4];"
        : "=r"(r[0]), "=r"(r[1]), "=r"(r[2]), "=r"(r[3]) : "r"(addr));
}
__device__ __forceinline__ void mma_f16(float* c, const uint32_t* a,
                                        uint32_t b0, uint32_t b1) {
    asm volatile(
        "mma.sync.aligned.m16n8k16.row.col.f32.f16.f16.f32 "
        "{%0,%1,%2,%3}, {%4,%5,%6,%7}, {%8,%9}, {%0,%1,%2,%3};"
        : "+f"(c[0]), "+f"(c[1]), "+f"(c[2]), "+f"(c[3])
        : "r"(a[0]), "r"(a[1]), "r"(a[2]), "r"(a[3]), "r"(b0), "r"(b1));
}

// ---------------- kernel: zero counters ----------------
__global__ void zero_cnt_kernel() {
    if (threadIdx.x < NEXP) g_cnt[threadIdx.x] = 0;
}

// ---------------- kernel: gating + x fp16 convert (fused) ----------------
__global__ void gating_kernel(const float* __restrict__ x,
                              const float* __restrict__ gW,
                              const float* __restrict__ gb) {
    __shared__ float sW[DIM * 9];
    int tid = threadIdx.x;
    for (int i = tid; i < DIM * NEXP; i += 256) {
        int d = i >> 3, e = i & 7;
        sW[d * 9 + e] = gW[i];
    }
    __syncthreads();

    int warp = tid >> 5, lane = tid & 31;
    int t = blockIdx.x * 8 + warp;
    const float* xrow = x + (size_t)t * DIM;
    __half*      xout = g_xh + (size_t)t * DIM;

    float acc[NEXP];
#pragma unroll
    for (int e = 0; e < NEXP; e++) acc[e] = 0.f;
#pragma unroll 8
    for (int i = 0; i < 32; i++) {
        int d = i * 32 + lane;
        float xv = xrow[d];
        xout[d] = __float2half_rn(xv);
        const float* w = &sW[d * 9];
#pragma unroll
        for (int e = 0; e < NEXP; e++) acc[e] += xv * w[e];
    }
#pragma unroll
    for (int e = 0; e < NEXP; e++) {
#pragma unroll
        for (int off = 16; off > 0; off >>= 1)
            acc[e] += __shfl_down_sync(0xFFFFFFFFu, acc[e], off);
    }

    if (lane == 0) {
        float s[NEXP], p[NEXP];
        float m = -1e30f;
#pragma unroll
        for (int e = 0; e < NEXP; e++) {
            s[e] = fmaxf(acc[e] + gb[e], 1e-4f);
            m = fmaxf(m, s[e]);
        }
        float sum = 0.f;
#pragma unroll
        for (int e = 0; e < NEXP; e++) { p[e] = expf(s[e] - m); sum += p[e]; }
        float inv = 1.f / sum;

        int b1 = 0, b2 = -1;
        float v1 = -1.f, v2 = -1.f;
#pragma unroll
        for (int e = 0; e < NEXP; e++) {
            float pe = p[e] * inv;
            if (pe > v1)      { v2 = v1; b2 = b1; v1 = pe; b1 = e; }
            else if (pe > v2) { v2 = pe; b2 = e; }
        }
        float c1 = fmaxf(v1, 0.1f);
        float c2 = fmaxf(v2, 0.1f);
        float a  = 1.f / ((c1 + c2) * 2.0f);
        float a1 = c1 * a, a2 = c2 * a;

        int s1 = atomicAdd(&g_cnt[b1], 1);
        g_tok[b1 * N_TOK + s1] = t;
        int s2 = atomicAdd(&g_cnt[b2], 1);
        g_tok[b2 * N_TOK + s2] = t;

        g_texp[2 * t] = b1;  g_texp[2 * t + 1] = b2;
        g_slot[2 * t] = s1;  g_slot[2 * t + 1] = s2;
        g_twt [2 * t] = a1;  g_twt [2 * t + 1] = a2;
    }
}

// ---------------- kernel: prefix offsets ----------------
__global__ void scan_kernel() {
    if (threadIdx.x == 0) {
        int o = 0;
        for (int e = 0; e < NEXP; e++) { g_off[e] = o; o += g_cnt[e]; }
    }
}

// ---------------- kernel: convert W to fp16 (k-major) ----------------
__global__ void convert_w_kernel(const float* __restrict__ eW) {
    size_t i = ((size_t)blockIdx.x * 256 + threadIdx.x) * 8;
    float4 v0 = *(const float4*)(eW + i);
    float4 v1 = *(const float4*)(eW + i + 4);
    __half2 h[4];
    h[0] = __floats2half2_rn(v0.x, v0.y);
    h[1] = __floats2half2_rn(v0.z, v0.w);
    h[2] = __floats2half2_rn(v1.x, v1.y);
    h[3] = __floats2half2_rn(v1.z, v1.w);
    *(uint4*)(g_wh + i) = *(uint4*)h;
}

// ---------------- kernel: fp16 mma.sync gathered GEMM ----------------
__global__ __launch_bounds__(256, 2)
void moe_gemm_mma() {
    extern __shared__ char smem[];
    int e     = blockIdx.z;
    int cnt   = g_cnt[e];
    int tile0 = blockIdx.y * BM;
    if (tile0 >= cnt) return;
    int f0  = blockIdx.x * BN;
    int tid = threadIdx.x;
    int wid = tid >> 5, lane = tid & 31;
    int g = lane >> 2, t = lane & 3;
    int wm = wid & 3, wn = wid >> 2;        // warp tile: 32 rows x 64 cols

    uint32_t sb = smem_u32(smem);
    int* s_tok = (int*)(smem + SM_TOK);
    for (int i = tid; i < BM; i += 256) {
        int r = tile0 + i;
        s_tok[i] = g_tok[e * N_TOK + (r < cnt ? r : 0)];
    }
    __syncthreads();

    // ---- loader base pointers ----
    int ar = tid >> 1, ah = tid & 1;                 // A: 2 threads/row, 32B each
    const __half* aSrc = g_xh + (size_t)s_tok[ar] * DIM + ah * 16;
    uint32_t      aDst = sb + SM_A + ar * A_ROWB + ah * 32;
    int bkr = tid >> 3, bc = tid & 7;                // B: 8 threads/k-row, 32B each
    const __half* bSrc = g_wh + ((size_t)e << 20) + (size_t)bkr * DIM + f0 + bc * 16;
    uint32_t      bDst = sb + SM_B + bkr * B_ROWB + bc * 32;

#define LOAD_STAGE(slot, s)                                              \
    do {                                                                 \
        int k0_ = (s) * BK;                                              \
        const __half* sa_ = aSrc + k0_;                                  \
        uint32_t da_ = aDst + (slot) * ASZ;                              \
        cp16(da_, sa_); cp16(da_ + 16, sa_ + 8);                         \
        const __half* sb_ = bSrc + (size_t)k0_ * DIM;                    \
        uint32_t db_ = bDst + (slot) * BSZ;                              \
        cp16(db_, sb_); cp16(db_ + 16, sb_ + 8);                         \
        CP_COMMIT();                                                     \
    } while (0)

    // ---- ldmatrix per-thread addresses ----
    int lrow  = lane & 15;          // row within 16-row group
    int lchnk = (lane >> 4) * 16;   // +16B for matrices 2,3
    uint32_t aLdBase = sb + SM_A + (uint32_t)((wm * 32 + lrow) * A_ROWB + lchnk);
    uint32_t bLdBase = sb + SM_B + (uint32_t)(lrow * B_ROWB + wn * 128 + lchnk);

    float acc[2][8][4];
#pragma unroll
    for (int i = 0; i < 2; i++)
#pragma unroll
        for (int j = 0; j < 8; j++)
#pragma unroll
            for (int q = 0; q < 4; q++) acc[i][j][q] = 0.f;

#pragma unroll
    for (int p = 0; p < NSTAGE - 1; p++) LOAD_STAGE(p, p);

    for (int s = 0; s < NK; s++) {
        CP_WAIT(NSTAGE - 2);
        __syncthreads();
        if (s + NSTAGE - 1 < NK) {
            LOAD_STAGE((s + NSTAGE - 1) % NSTAGE, s + NSTAGE - 1);
        } else {
            CP_COMMIT();
        }

        int slot = s % NSTAGE;
        uint32_t aL = aLdBase + slot * ASZ;
        uint32_t bL = bLdBase + slot * BSZ;
#pragma unroll
        for (int ks = 0; ks < 2; ks++) {
            uint32_t a[2][4], bq[4][4];
#pragma unroll
            for (int i = 0; i < 2; i++)
                ldsm4(a[i], aL + i * (16 * A_ROWB) + ks * 32);
#pragma unroll
            for (int jj = 0; jj < 4; jj++)
                ldsm4t(bq[jj], bL + ks * (16 * B_ROWB) + jj * 32);
#pragma unroll
            for (int jj = 0; jj < 4; jj++)
#pragma unroll
                for (int i = 0; i < 2; i++) {
                    mma_f16(acc[i][2 * jj],     a[i], bq[jj][0], bq[jj][1]);
                    mma_f16(acc[i][2 * jj + 1], a[i], bq[jj][2], bq[jj][3]);
                }
        }
    }

    // ---- epilogue: write fp16 staging y ----
    int rowbase = g_off[e] + tile0;
#pragma unroll
    for (int i = 0; i < 2; i++) {
        int r0 = wm * 32 + i * 16 + g;
#pragma unroll
        for (int j = 0; j < 8; j++) {
            int col = f0 + wn * 64 + j * 8 + t * 2;
            if (tile0 + r0 < cnt) {
                __half2 v = __floats2half2_rn(acc[i][j][0], acc[i][j][1]);
                *(__half2*)(g_yh + (size_t)(rowbase + r0) * DIM + col) = v;
            }
            if (tile0 + r0 + 8 < cnt) {
                __half2 v = __floats2half2_rn(acc[i][j][2], acc[i][j][3]);
                *(__half2*)(g_yh + (size_t)(rowbase + r0 + 8) * DIM + col) = v;
            }
        }
    }
#undef LOAD_STAGE
}

// ---------------- kernel: combine ----------------
__global__ void combine_kernel(const float* __restrict__ eb,
                               float* __restrict__ out) {
    int tid = blockIdx.x * 256 + threadIdx.x;
    int t = tid >> 6, j = tid & 63;
    int e1 = g_texp[2 * t], e2 = g_texp[2 * t + 1];
    float a1 = g_twt[2 * t], a2 = g_twt[2 * t + 1];
    int r1 = g_off[e1] + g_slot[2 * t];
    int r2 = g_off[e2] + g_slot[2 * t + 1];
    const __half2* y1 = (const __half2*)(g_yh + (size_t)r1 * DIM);
    const __half2* y2 = (const __half2*)(g_yh + (size_t)r2 * DIM);
    const float4* b1 = (const float4*)(eb + (size_t)e1 * DIM);
    const float4* b2 = (const float4*)(eb + (size_t)e2 * DIM);
    float4* o = (float4*)(out + (size_t)t * DIM);
#pragma unroll
    for (int q = 0; q < 4; q++) {
        int f = j + 64 * q;                 // float4 index (0..255)
        float2 va = __half22float2(y1[2 * f]);
        float2 vb = __half22float2(y1[2 * f + 1]);
        float2 wa = __half22float2(y2[2 * f]);
        float2 wb = __half22float2(y2[2 * f + 1]);
        float4 c1 = b1[f], c2 = b2[f];
        float4 r;
        r.x = a1 * (va.x + c1.x) + a2 * (wa.x + c2.x);
        r.y = a1 * (va.y + c1.y) + a2 * (wa.y + c2.y);
        r.z = a1 * (vb.x + c1.z) + a2 * (wb.x + c2.z);
        r.w = a1 * (vb.y + c1.w) + a2 * (wb.y + c2.w);
        o[f] = r;
    }
}

// ---------------- launch ----------------
extern "C" void kernel_launch(void* const* d_in, const int* in_sizes, int n_in,
                              void* d_out, int out_size) {
    const float* x  = (const float*)d_in[0];
    const float* gW = (const float*)d_in[1];
    const float* gb = (const float*)d_in[2];
    const float* eW = (const float*)d_in[3];
    const float* eb = (const float*)d_in[4];
    float* out = (float*)d_out;
    (void)in_sizes; (void)n_in; (void)out_size;

    zero_cnt_kernel<<<1, 32>>>();
    gating_kernel<<<N_TOK / 8, 256>>>(x, gW, gb);
    scan_kernel<<<1, 1>>>();
    convert_w_kernel<<<(NEXP * DIM * DIM / 8) / 256, 256>>>(eW);

    cudaFuncSetAttribute(moe_gemm_mma,
                         cudaFuncAttributeMaxDynamicSharedMemorySize, SMEM_ALLOC);
    moe_gemm_mma<<<dim3(DIM / BN, N_TOK / BM, NEXP), 256, SMEM_ALLOC>>>();

    combine_kernel<<<(N_TOK * 64) / 256, 256>>>(eb, out);
}